// round 16
// baseline (speedup 1.0000x reference)
#include <cuda_runtime.h>
#include <cuda_fp16.h>
#include <math.h>

#define N_DOC 10000
#define N_WORD 20000
#define N_ENT 10000
#define N_POS 60
#define DIM 128
#define D_POS_IN 60
#define D_WEMB 300
#define E11 320000
#define E22 160000
#define E33 3600
#define E01 300000
#define E02 100000
#define E03 150000

typedef unsigned long long ull;

// merged offsets (compile time)
enum { CU11 = 0, CU22 = 20000, CU33 = 30000, CU01 = 30060, CU02 = 40060, CU03 = 50060, CU_TOT = 60060 };
enum { RP11 = 0, RP22 = 20001, RP33 = 30002, RP01 = 30063, RP02 = 40064, RP03 = 50065, RP_TOT = 60066 };
enum { EO11 = 0, EO22 = 320000, EO33 = 480000, EO01 = 483600, EO02 = 783600, EO03 = 883600, E_TOT = 1033600 };

// hist: 4 edges/thread, six graphs; then t3 gemm1; then f1/f2 fp16 conversion
enum { H11 = 313, H22 = 470, H33 = 474, H01 = 767, H02 = 865, H03 = 1012,
       HT3 = H03 + 15, HF1 = HT3 + 625, HF2 = HF1 + 313 };

// stageA/C: dual-row warps for t1/t2 (16 rows/block), single-row for t3
enum { A_T1 = 1250, A_T2 = A_T1 + 625, A_TOT = A_T2 + 8 };

// stageB: gemm blocks first (FMA-bound), then warp-per-row wemb-agg blocks (8 rows/block)
enum { BG1 = 313, BG2 = 470, BG3 = 471, B_AGG0 = 471, B_TOT = B_AGG0 + 1250 };

// stageD layout: 448 threads (14 warps), warp-per-row everywhere
enum { D_OUT1 = 715, D_OUT2 = D_OUT1 + 715, D_OUT3 = D_OUT2 + 715, D_ZERO = D_OUT3 + 59 };

// ---------------- scratch ----------------
__device__ int   g_cu[CU_TOT];
__device__ int   g_rp[RP_TOT];
__device__ int2  g_ecv[E_TOT];   // interleaved (col, val_bits)

__device__ float g_h1a[N_WORD * DIM];
__device__ float g_h2a[N_ENT * DIM];
__device__ float g_t3a[N_POS * DIM];
__device__ float g_t3b[N_POS * DIM];
__device__ float g_w2agg[N_DOC * D_WEMB];   // precomputed A02 @ word_emb

// fp16 feature tensors (row = 32 uint2 = 128 halves)
__device__ uint2 g_f1h[N_WORD * 32];
__device__ uint2 g_f2h[N_ENT * 32];
__device__ uint2 g_t1h[N_WORD * 32];
__device__ uint2 g_t2h[N_ENT * 32];
__device__ uint2 g_h1h[N_WORD * 32];
__device__ uint2 g_h2h[N_ENT * 32];
__device__ uint2 g_h3h[N_POS * 32];

// ---------------- packed fp32 / fp16 helpers ----------------
__device__ __forceinline__ ull fma2(ull a, ull b, ull c) {
    ull d;
    asm("fma.rn.f32x2 %0, %1, %2, %3;" : "=l"(d) : "l"(a), "l"(b), "l"(c));
    return d;
}
__device__ __forceinline__ ull pack2(float lo, float hi) {
    ull d;
    asm("mov.b64 %0, {%1, %2};" : "=l"(d) : "f"(lo), "f"(hi));
    return d;
}
__device__ __forceinline__ float2 unpack2(ull v) {
    float2 r;
    asm("mov.b64 {%0, %1}, %2;" : "=f"(r.x), "=f"(r.y) : "l"(v));
    return r;
}
__device__ __forceinline__ float4 h4f(uint2 p) {
    float2 lo = __half22float2(*reinterpret_cast<const __half2*>(&p.x));
    float2 hi = __half22float2(*reinterpret_cast<const __half2*>(&p.y));
    return make_float4(lo.x, lo.y, hi.x, hi.y);
}
__device__ __forceinline__ uint2 f4h(float4 a) {
    __half2 lo = __floats2half2_rn(a.x, a.y);
    __half2 hi = __floats2half2_rn(a.z, a.w);
    uint2 p;
    p.x = *reinterpret_cast<unsigned int*>(&lo);
    p.y = *reinterpret_cast<unsigned int*>(&hi);
    return p;
}
__device__ __forceinline__ void fma4(float4& acc, float v, float4 a) {
    acc.x = fmaf(v, a.x, acc.x);
    acc.y = fmaf(v, a.y, acc.y);
    acc.z = fmaf(v, a.z, acc.z);
    acc.w = fmaf(v, a.w, acc.w);
}

// ---------------- CSR build ----------------
__global__ void k_hist_all(const int* __restrict__ r11, const int* __restrict__ r22,
                           const int* __restrict__ r33, const int* __restrict__ r01,
                           const int* __restrict__ r02, const int* __restrict__ r03,
                           const float* __restrict__ f3, const float* __restrict__ W3,
                           const float* __restrict__ b3, const float* __restrict__ f1,
                           const float* __restrict__ f2) {
    int b = blockIdx.x, t = threadIdx.x;
    if (b >= H03) {
        if (b < HT3) {
            int r0 = (b - H03) * 4;
#pragma unroll
            for (int i = t; i < 4 * DIM; i += 256) {
                int r = r0 + (i >> 7), c = i & 127;
                float a = b3[c];
#pragma unroll 4
                for (int k = 0; k < D_POS_IN; k++)
                    a = fmaf(f3[r * D_POS_IN + k], W3[k * DIM + c], a);
                g_t3a[r * DIM + c] = a;
            }
        } else if (b < HF1) {
            int idx0 = (b - HT3) * 1024 + t;
            const float4* src = (const float4*)f1;
#pragma unroll
            for (int j = 0; j < 4; j++) {
                int idx = idx0 + j * 256;
                g_f1h[idx] = f4h(src[idx]);
            }
        } else {
            int idx0 = (b - HF1) * 1024 + t;
            const float4* src = (const float4*)f2;
#pragma unroll
            for (int j = 0; j < 4; j++) {
                int idx = idx0 + j * 256;
                if (idx < N_ENT * 32) g_f2h[idx] = f4h(src[idx]);
            }
        }
        return;
    }
    const int* rows; int E, off, b0;
    if (b < H11)      { rows = r11; E = E11; off = CU11; b0 = 0; }
    else if (b < H22) { rows = r22; E = E22; off = CU22; b0 = H11; }
    else if (b < H33) { rows = r33; E = E33; off = CU33; b0 = H22; }
    else if (b < H01) { rows = r01; E = E01; off = CU01; b0 = H33; }
    else if (b < H02) { rows = r02; E = E02; off = CU02; b0 = H01; }
    else              { rows = r03; E = E03; off = CU03; b0 = H02; }
    int e0 = (b - b0) * 1024 + t;
#pragma unroll
    for (int j = 0; j < 4; j++) {
        int e = e0 + j * 256;
        if (e < E) atomicAdd(&g_cu[off + rows[e]], 1);
    }
}

__global__ void k_scan_all() {
    __shared__ int wsum[32];
    const int ns[6]  = {N_WORD, N_ENT, N_POS, N_DOC, N_DOC, N_DOC};
    const int cuo[6] = {CU11, CU22, CU33, CU01, CU02, CU03};
    const int rpo[6] = {RP11, RP22, RP33, RP01, RP02, RP03};
    int g = blockIdx.x;
    int n = ns[g];
    int* cnt = g_cu + cuo[g];
    int* rp  = g_rp + rpo[g];
    int tid = threadIdx.x;  // 1024
    int chunk = (n + 1023) >> 10;
    int base = tid * chunk;
    int end = base + chunk; if (end > n) end = n;
    int s = 0;
    for (int i = base; i < end && i >= base; i++) s += cnt[i];
    int lane = tid & 31, w = tid >> 5;
    int v = s;
#pragma unroll
    for (int o = 1; o < 32; o <<= 1) { int u = __shfl_up_sync(~0u, v, o); if (lane >= o) v += u; }
    if (lane == 31) wsum[w] = v;
    __syncthreads();
    if (w == 0) {
        int x = wsum[lane];
#pragma unroll
        for (int o = 1; o < 32; o <<= 1) { int u = __shfl_up_sync(~0u, x, o); if (lane >= o) x += u; }
        wsum[lane] = x;
    }
    __syncthreads();
    int excl = v - s + (w > 0 ? wsum[w - 1] : 0);
    int run = excl;
    for (int i = base; i < end && i >= base; i++) {
        int c = cnt[i];
        cnt[i] = run;
        rp[i] = run;
        run += c;
    }
    if (end == n || base >= n) rp[n] = run;
}

__device__ __forceinline__ void scatter_range(const int* __restrict__ rows, const int* __restrict__ cols,
                                              const float* __restrict__ vals, int E, int cuoff, int eoff,
                                              int rel_b, int t) {
    int e0 = rel_b * 1024 + t;
#pragma unroll
    for (int j = 0; j < 4; j++) {
        int e = e0 + j * 256;
        if (e < E) {
            int slot = atomicAdd(&g_cu[cuoff + rows[e]], 1);
            g_ecv[eoff + slot] = make_int2(cols[e], __float_as_int(vals[e]));
        }
    }
}

__global__ void k_scatter_all(const int* __restrict__ r11, const int* __restrict__ c11, const float* __restrict__ v11,
                              const int* __restrict__ r22, const int* __restrict__ c22, const float* __restrict__ v22,
                              const int* __restrict__ r33, const int* __restrict__ c33, const float* __restrict__ v33,
                              const int* __restrict__ r01, const int* __restrict__ c01, const float* __restrict__ v01,
                              const int* __restrict__ r02, const int* __restrict__ c02, const float* __restrict__ v02,
                              const int* __restrict__ r03, const int* __restrict__ c03, const float* __restrict__ v03) {
    int b = blockIdx.x, t = threadIdx.x;
    if (b < H11)      scatter_range(r11, c11, v11, E11, CU11, EO11, b, t);
    else if (b < H22) scatter_range(r22, c22, v22, E22, CU22, EO22, b - H11, t);
    else if (b < H33) scatter_range(r33, c33, v33, E33, CU33, EO33, b - H22, t);
    else if (b < H01) scatter_range(r01, c01, v01, E01, CU01, EO01, b - H33, t);
    else if (b < H02) scatter_range(r02, c02, v02, E02, CU02, EO02, b - H01, t);
    else              scatter_range(r03, c03, v03, E03, CU03, EO03, b - H02, t);
}

// ---------------- spMM cores ----------------
__device__ __forceinline__ float4 spmm_row_f4(const int* __restrict__ rp, const int2* __restrict__ ecv,
                                              const float4* __restrict__ x4, int row, int lane) {
    int s = rp[row], e = rp[row + 1];
    float4 acc = make_float4(0.f, 0.f, 0.f, 0.f);
    int i = s;
    for (; i + 3 < e; i += 4) {
        int2 e0 = ecv[i], e1 = ecv[i + 1], e2 = ecv[i + 2], e3 = ecv[i + 3];
        float4 a = x4[(size_t)e0.x * 32 + lane];
        float4 b = x4[(size_t)e1.x * 32 + lane];
        float4 c = x4[(size_t)e2.x * 32 + lane];
        float4 d = x4[(size_t)e3.x * 32 + lane];
        fma4(acc, __int_as_float(e0.y), a);
        fma4(acc, __int_as_float(e1.y), b);
        fma4(acc, __int_as_float(e2.y), c);
        fma4(acc, __int_as_float(e3.y), d);
    }
    for (; i < e; i++) {
        int2 e0 = ecv[i];
        fma4(acc, __int_as_float(e0.y), x4[(size_t)e0.x * 32 + lane]);
    }
    return acc;
}

// finish a row from position i (x4 + scalar tail)
__device__ __forceinline__ float4 spmm_fin_h4(const int2* __restrict__ ecv, const uint2* __restrict__ xh,
                                              int i, int e, int lane, float4 acc) {
    for (; i + 3 < e; i += 4) {
        int2 e0 = ecv[i], e1 = ecv[i + 1], e2 = ecv[i + 2], e3 = ecv[i + 3];
        uint2 pa = xh[(size_t)e0.x * 32 + lane];
        uint2 pb = xh[(size_t)e1.x * 32 + lane];
        uint2 pc = xh[(size_t)e2.x * 32 + lane];
        uint2 pd = xh[(size_t)e3.x * 32 + lane];
        fma4(acc, __int_as_float(e0.y), h4f(pa));
        fma4(acc, __int_as_float(e1.y), h4f(pb));
        fma4(acc, __int_as_float(e2.y), h4f(pc));
        fma4(acc, __int_as_float(e3.y), h4f(pd));
    }
    for (; i < e; i++) {
        int2 e0 = ecv[i];
        fma4(acc, __int_as_float(e0.y), h4f(xh[(size_t)e0.x * 32 + lane]));
    }
    return acc;
}

__device__ __forceinline__ float4 spmm_row_h4(const int* __restrict__ rp, const int2* __restrict__ ecv,
                                              const uint2* __restrict__ xh, int row, int lane) {
    return spmm_fin_h4(ecv, xh, rp[row], rp[row + 1], lane, make_float4(0.f, 0.f, 0.f, 0.f));
}

// dual-row: two interleaved edge streams -> 8 independent gathers in flight
__device__ __forceinline__ void spmm_row2_h4(const int* __restrict__ rp, const int2* __restrict__ ecv,
                                             const uint2* __restrict__ xh, int r0, int r1, int lane,
                                             float4& acc0, float4& acc1) {
    int i0 = rp[r0], e0 = rp[r0 + 1];
    int i1 = rp[r1], e1 = rp[r1 + 1];
    acc0 = make_float4(0.f, 0.f, 0.f, 0.f);
    acc1 = make_float4(0.f, 0.f, 0.f, 0.f);
    while (i0 + 3 < e0 && i1 + 3 < e1) {
        int2 a0 = ecv[i0], a1 = ecv[i0 + 1], a2 = ecv[i0 + 2], a3 = ecv[i0 + 3];
        int2 b0 = ecv[i1], b1 = ecv[i1 + 1], b2 = ecv[i1 + 2], b3 = ecv[i1 + 3];
        uint2 pa0 = xh[(size_t)a0.x * 32 + lane];
        uint2 pa1 = xh[(size_t)a1.x * 32 + lane];
        uint2 pa2 = xh[(size_t)a2.x * 32 + lane];
        uint2 pa3 = xh[(size_t)a3.x * 32 + lane];
        uint2 pb0 = xh[(size_t)b0.x * 32 + lane];
        uint2 pb1 = xh[(size_t)b1.x * 32 + lane];
        uint2 pb2 = xh[(size_t)b2.x * 32 + lane];
        uint2 pb3 = xh[(size_t)b3.x * 32 + lane];
        fma4(acc0, __int_as_float(a0.y), h4f(pa0));
        fma4(acc1, __int_as_float(b0.y), h4f(pb0));
        fma4(acc0, __int_as_float(a1.y), h4f(pa1));
        fma4(acc1, __int_as_float(b1.y), h4f(pb1));
        fma4(acc0, __int_as_float(a2.y), h4f(pa2));
        fma4(acc1, __int_as_float(b2.y), h4f(pb2));
        fma4(acc0, __int_as_float(a3.y), h4f(pa3));
        fma4(acc1, __int_as_float(b3.y), h4f(pb3));
        i0 += 4; i1 += 4;
    }
    acc0 = spmm_fin_h4(ecv, xh, i0, e0, lane, acc0);
    acc1 = spmm_fin_h4(ecv, xh, i1, e1, lane, acc1);
}

__device__ __forceinline__ void store_relu_f4(float4 acc, float* __restrict__ y, int row, int lane) {
    ((float4*)y)[(size_t)row * 32 + lane] =
        make_float4(fmaxf(acc.x, 0.f), fmaxf(acc.y, 0.f), fmaxf(acc.z, 0.f), fmaxf(acc.w, 0.f));
}

__device__ __forceinline__ void store_relu_h4(float4 a, uint2* __restrict__ y, int row, int lane) {
    y[(size_t)row * 32 + lane] =
        f4h(make_float4(fmaxf(a.x, 0.f), fmaxf(a.y, 0.f), fmaxf(a.z, 0.f), fmaxf(a.w, 0.f)));
}

__device__ __forceinline__ void store_norm_f4(float4 acc, float* __restrict__ y, int row, int lane) {
    float sq = acc.x * acc.x + acc.y * acc.y + acc.z * acc.z + acc.w * acc.w;
#pragma unroll
    for (int o = 16; o > 0; o >>= 1) sq += __shfl_xor_sync(~0u, sq, o);
    float s = 1.f / (sqrtf(sq) + 1e-9f);
    ((float4*)y)[(size_t)row * 32 + lane] = make_float4(acc.x * s, acc.y * s, acc.z * s, acc.w * s);
}

// ---------------- Stage A: dual-row spmm1(t1,t2) from fp16 + t3 spmm1 ----------------
__global__ void k_stageA() {
    int b = blockIdx.x, t = threadIdx.x, lane = t & 31, w = t >> 5;
    if (b < A_T1) {
        int r0 = b * 16 + w * 2;
        float4 acc0, acc1;
        spmm_row2_h4(g_rp + RP11, g_ecv + EO11, g_f1h, r0, r0 + 1, lane, acc0, acc1);
        store_relu_f4(acc0, g_h1a, r0, lane);
        store_relu_f4(acc1, g_h1a, r0 + 1, lane);
    } else if (b < A_T2) {
        int r0 = (b - A_T1) * 16 + w * 2;
        float4 acc0, acc1;
        spmm_row2_h4(g_rp + RP22, g_ecv + EO22, g_f2h, r0, r0 + 1, lane, acc0, acc1);
        store_relu_f4(acc0, g_h2a, r0, lane);
        store_relu_f4(acc1, g_h2a, r0 + 1, lane);
    } else {
        int row = (b - A_T2) * 8 + w;
        if (row < N_POS) {
            float4 acc = spmm_row_f4(g_rp + RP33, g_ecv + EO33, (const float4*)g_t3a, row, lane);
            store_relu_f4(acc, g_t3b, row, lane);
        }
    }
}

// ---------------- FFMA2 GEMM, 64-row tiles: y = x @ W + b (fp32 or fp16 output) ----------------
template <bool HALF_OUT>
__device__ __forceinline__ void gemm64_f2(const float* __restrict__ x, const float* __restrict__ W,
                                          const float* __restrict__ bias, float* __restrict__ y,
                                          uint2* __restrict__ yh, int nrows, int r0, float* xs) {
    int t = threadIdx.x;
    const float4* x4 = (const float4*)x;
    float4* xs4 = (float4*)xs;
    for (int i = t; i < 64 * 32; i += 256) {
        int gr = r0 + (i >> 5);
        xs4[i] = (gr < nrows) ? x4[(size_t)gr * 32 + (i & 31)] : make_float4(0.f, 0.f, 0.f, 0.f);
    }
    __syncthreads();
    int cg = t & 31;
    int rg = t >> 5;
    const float4* Wc = (const float4*)W;
    float4 b4 = ((const float4*)bias)[cg];
    ull acc[8][2];
#pragma unroll
    for (int r = 0; r < 8; r++) { acc[r][0] = pack2(b4.x, b4.y); acc[r][1] = pack2(b4.z, b4.w); }
    const float4* xr = xs4 + rg * 8 * 32;
    for (int k4 = 0; k4 < 32; k4++) {
        float4 xv[8];
#pragma unroll
        for (int r = 0; r < 8; r++) xv[r] = xr[r * 32 + k4];
#pragma unroll
        for (int kk = 0; kk < 4; kk++) {
            float4 wv = Wc[(k4 * 4 + kk) * 32 + cg];
            ull wp0 = pack2(wv.x, wv.y);
            ull wp1 = pack2(wv.z, wv.w);
#pragma unroll
            for (int r = 0; r < 8; r++) {
                float xsv = (kk == 0) ? xv[r].x : (kk == 1) ? xv[r].y : (kk == 2) ? xv[r].z : xv[r].w;
                ull xp = pack2(xsv, xsv);
                acc[r][0] = fma2(xp, wp0, acc[r][0]);
                acc[r][1] = fma2(xp, wp1, acc[r][1]);
            }
        }
    }
#pragma unroll
    for (int r = 0; r < 8; r++) {
        int gr = r0 + rg * 8 + r;
        if (gr < nrows) {
            float2 lo = unpack2(acc[r][0]);
            float2 hi = unpack2(acc[r][1]);
            if (HALF_OUT) {
                yh[(size_t)gr * 32 + cg] = f4h(make_float4(lo.x, lo.y, hi.x, hi.y));
            } else {
                ((float4*)y)[(size_t)gr * 32 + cg] = make_float4(lo.x, lo.y, hi.x, hi.y);
            }
        }
    }
}

// ---------------- Stage B: gemms (FMA-bound) + warp-per-row wemb doc-aggregation ----------------
__global__ void k_stageB(const float* __restrict__ wemb,
                         const float* __restrict__ W1_2, const float* __restrict__ b1_2,
                         const float* __restrict__ W2_2, const float* __restrict__ b2_2,
                         const float* __restrict__ W3_2, const float* __restrict__ b3_2) {
    __shared__ float xs[64 * 128];
    int b = blockIdx.x, t = threadIdx.x;
    if (b < BG1)      { gemm64_f2<true>(g_h1a, W1_2, b1_2, nullptr, g_t1h, N_WORD, b * 64, xs); return; }
    else if (b < BG2) { gemm64_f2<true>(g_h2a, W2_2, b2_2, nullptr, g_t2h, N_ENT, (b - BG1) * 64, xs); return; }
    else if (b < BG3) { gemm64_f2<false>(g_t3b, W3_2, b3_2, g_t3a, nullptr, N_POS, 0, xs); return; }
    int lane = t & 31, w = t >> 5;
    int row = (b - B_AGG0) * 8 + w;
    if (row < N_DOC) {
        int s = g_rp[RP02 + row], e = g_rp[RP02 + row + 1];
        float acc[10];
#pragma unroll
        for (int j = 0; j < 10; j++) acc[j] = 0.f;
        for (int i = s; i < e; i++) {
            int2 ed = g_ecv[EO02 + i];
            float v = __int_as_float(ed.y);
            const float* wrow = wemb + (size_t)ed.x * D_WEMB;
#pragma unroll
            for (int j = 0; j < 10; j++) {
                int c = lane + j * 32;
                if (c < D_WEMB) acc[j] = fmaf(v, wrow[c], acc[j]);
            }
        }
        float* orow = g_w2agg + (size_t)row * D_WEMB;
#pragma unroll
        for (int j = 0; j < 10; j++) {
            int c = lane + j * 32;
            if (c < D_WEMB) orow[c] = acc[j];
        }
    }
}

// ---------------- Stage C: dual-row spmm2 from fp16 t1/t2 -> fp16; t3 single ----------------
__global__ void k_stageC() {
    int b = blockIdx.x, t = threadIdx.x, lane = t & 31, w = t >> 5;
    if (b < A_T1) {
        int r0 = b * 16 + w * 2;
        float4 acc0, acc1;
        spmm_row2_h4(g_rp + RP11, g_ecv + EO11, g_t1h, r0, r0 + 1, lane, acc0, acc1);
        store_relu_h4(acc0, g_h1h, r0, lane);
        store_relu_h4(acc1, g_h1h, r0 + 1, lane);
    } else if (b < A_T2) {
        int r0 = (b - A_T1) * 16 + w * 2;
        float4 acc0, acc1;
        spmm_row2_h4(g_rp + RP22, g_ecv + EO22, g_t2h, r0, r0 + 1, lane, acc0, acc1);
        store_relu_h4(acc0, g_h2h, r0, lane);
        store_relu_h4(acc1, g_h2h, r0 + 1, lane);
    } else {
        int row = (b - A_T2) * 8 + w;
        if (row < N_POS) {
            float4 acc = spmm_row_f4(g_rp + RP33, g_ecv + EO33, (const float4*)g_t3a, row, lane);
            store_relu_h4(acc, g_h3h, row, lane);
        }
    }
}

// ---------------- Stage D (448 thr, 14 warps): warp-per-row out1/out2/out3 (fp16 gathers) ----------------
__global__ void k_stageD(float* __restrict__ out) {
    int b = blockIdx.x, t = threadIdx.x, lane = t & 31, w = t >> 5;
    if (b < D_OUT1) {
        int row = b * 14 + w;
        if (row < N_DOC) {
            float4 acc = spmm_row_h4(g_rp + RP01, g_ecv + EO01, g_h1h, row, lane);
            store_norm_f4(acc, out, row, lane);
        }
    } else if (b < D_OUT2) {
        int row = (b - D_OUT1) * 14 + w;
        if (row < N_DOC) {
            float4 acc = spmm_row_h4(g_rp + RP02, g_ecv + EO02, g_h2h, row, lane);
            float sq = acc.x * acc.x + acc.y * acc.y + acc.z * acc.z + acc.w * acc.w;
            float wv[10];
            const float* wrow = g_w2agg + (size_t)row * D_WEMB;
#pragma unroll
            for (int j = 0; j < 10; j++) {
                int c = lane + j * 32;
                wv[j] = (c < D_WEMB) ? wrow[c] : 0.f;
                sq = fmaf(wv[j], wv[j], sq);
            }
#pragma unroll
            for (int o = 16; o > 0; o >>= 1) sq += __shfl_xor_sync(~0u, sq, o);
            float sc = 1.f / (sqrtf(sq) + 1e-9f);
            float* orow = out + (size_t)N_DOC * DIM + (size_t)row * (DIM + D_WEMB);
            ((float4*)orow)[lane] = make_float4(acc.x * sc, acc.y * sc, acc.z * sc, acc.w * sc);
#pragma unroll
            for (int j = 0; j < 10; j++) {
                int c = lane + j * 32;
                if (c < D_WEMB) orow[DIM + c] = wv[j] * sc;
            }
        }
    } else if (b < D_OUT3) {
        int row = (b - D_OUT2) * 14 + w;
        if (row < N_DOC) {
            float4 acc = spmm_row_h4(g_rp + RP03, g_ecv + EO03, g_h3h, row, lane);
            float* out3 = out + (size_t)N_DOC * (DIM + DIM + D_WEMB);
            store_norm_f4(acc, out3, row, lane);
        }
    } else {
        int base = (b - D_OUT3) * 1024;
#pragma unroll
        for (int i = t; i < 1024; i += 448) {
            int idx = base + i;
            if (idx < CU_TOT) g_cu[idx] = 0;
        }
    }
}

// ---------------- host ----------------
extern "C" void kernel_launch(void* const* d_in, const int* in_sizes, int n_in,
                              void* d_out, int out_size) {
    const float* f1 = (const float*)d_in[0];
    const float* f2 = (const float*)d_in[1];
    const float* f3 = (const float*)d_in[2];
    const float* wemb = (const float*)d_in[3];
    const int* a11_r = (const int*)d_in[4];  const int* a11_c = (const int*)d_in[5];  const float* a11_v = (const float*)d_in[6];
    const int* a22_r = (const int*)d_in[7];  const int* a22_c = (const int*)d_in[8];  const float* a22_v = (const float*)d_in[9];
    const int* a33_r = (const int*)d_in[10]; const int* a33_c = (const int*)d_in[11]; const float* a33_v = (const float*)d_in[12];
    const int* a01_r = (const int*)d_in[13]; const int* a01_c = (const int*)d_in[14]; const float* a01_v = (const float*)d_in[15];
    const int* a02_r = (const int*)d_in[16]; const int* a02_c = (const int*)d_in[17]; const float* a02_v = (const float*)d_in[18];
    const int* a03_r = (const int*)d_in[19]; const int* a03_c = (const int*)d_in[20]; const float* a03_v = (const float*)d_in[21];
    const float* W3 = (const float*)d_in[22];   const float* b3 = (const float*)d_in[23];
    const float* W1_2 = (const float*)d_in[24]; const float* b1_2 = (const float*)d_in[25];
    const float* W2_2 = (const float*)d_in[26]; const float* b2_2 = (const float*)d_in[27];
    const float* W3_2 = (const float*)d_in[28]; const float* b3_2 = (const float*)d_in[29];

    float* out = (float*)d_out;

    // CSR build (g_cu zeroed by BSS init on first run, by stageD on every replay)
    k_hist_all<<<HF2, 256>>>(a11_r, a22_r, a33_r, a01_r, a02_r, a03_r, f3, W3, b3, f1, f2);
    k_scan_all<<<6, 1024>>>();
    k_scatter_all<<<H03, 256>>>(a11_r, a11_c, a11_v, a22_r, a22_c, a22_v,
                                a33_r, a33_c, a33_v, a01_r, a01_c, a01_v,
                                a02_r, a02_c, a02_v, a03_r, a03_c, a03_v);

    // compute
    k_stageA<<<A_TOT, 256>>>();
    k_stageB<<<B_TOT, 256>>>(wemb, W1_2, b1_2, W2_2, b2_2, W3_2, b3_2);
    k_stageC<<<A_TOT, 256>>>();
    k_stageD<<<D_ZERO, 448>>>(out);
}

// round 17
// speedup vs baseline: 1.0382x; 1.0382x over previous
#include <cuda_runtime.h>
#include <cuda_fp16.h>
#include <math.h>

#define N_DOC 10000
#define N_WORD 20000
#define N_ENT 10000
#define N_POS 60
#define DIM 128
#define D_POS_IN 60
#define D_WEMB 300
#define E11 320000
#define E22 160000
#define E33 3600
#define E01 300000
#define E02 100000
#define E03 150000

typedef unsigned long long ull;

// merged offsets (compile time)
enum { CU11 = 0, CU22 = 20000, CU33 = 30000, CU01 = 30060, CU02 = 40060, CU03 = 50060, CU_TOT = 60060 };
enum { RP11 = 0, RP22 = 20001, RP33 = 30002, RP01 = 30063, RP02 = 40064, RP03 = 50065, RP_TOT = 60066 };
enum { EO11 = 0, EO22 = 320000, EO33 = 480000, EO01 = 483600, EO02 = 783600, EO03 = 883600, E_TOT = 1033600 };

// hist: 4 edges/thread, six graphs; + t3 gemm1 (15 blocks)
enum { H11 = 313, H22 = 470, H33 = 474, H01 = 767, H02 = 865, H03 = 1012, HT3 = H03 + 15 };

// scan launch: 6 scan blocks + f1/f2 fp16 conversion blocks (chip otherwise idle here)
enum { SC_F1 = 6, SC_F2 = SC_F1 + 625, SC_TOT = SC_F2 + 313 };

// stageB: gemm blocks first (FMA-bound), then warp-per-row wemb-agg blocks (8 rows/block)
enum { BG1 = 313, BG2 = 470, BG3 = 471, B_AGG0 = 471, B_TOT = B_AGG0 + 1250 };

// stageD layout: 448 threads (14 warps), warp-per-row everywhere
enum { D_OUT1 = 715, D_OUT2 = D_OUT1 + 715, D_OUT3 = D_OUT2 + 715, D_ZERO = D_OUT3 + 59 };

// ---------------- scratch ----------------
__device__ int   g_cu[CU_TOT];
__device__ int   g_rp[RP_TOT];
__device__ int2  g_ecv[E_TOT];   // interleaved (col, val_bits)

__device__ float g_h1a[N_WORD * DIM];
__device__ float g_h2a[N_ENT * DIM];
__device__ float g_t3a[N_POS * DIM];
__device__ float g_t3b[N_POS * DIM];
__device__ float g_w2agg[N_DOC * D_WEMB];   // precomputed A02 @ word_emb

// fp16 feature tensors (row = 32 uint2 = 128 halves)
__device__ uint2 g_f1h[N_WORD * 32];
__device__ uint2 g_f2h[N_ENT * 32];
__device__ uint2 g_t1h[N_WORD * 32];
__device__ uint2 g_t2h[N_ENT * 32];
__device__ uint2 g_h1h[N_WORD * 32];
__device__ uint2 g_h2h[N_ENT * 32];
__device__ uint2 g_h3h[N_POS * 32];

// ---------------- packed fp32 / fp16 helpers ----------------
__device__ __forceinline__ ull fma2(ull a, ull b, ull c) {
    ull d;
    asm("fma.rn.f32x2 %0, %1, %2, %3;" : "=l"(d) : "l"(a), "l"(b), "l"(c));
    return d;
}
__device__ __forceinline__ ull pack2(float lo, float hi) {
    ull d;
    asm("mov.b64 %0, {%1, %2};" : "=l"(d) : "f"(lo), "f"(hi));
    return d;
}
__device__ __forceinline__ float2 unpack2(ull v) {
    float2 r;
    asm("mov.b64 {%0, %1}, %2;" : "=f"(r.x), "=f"(r.y) : "l"(v));
    return r;
}
__device__ __forceinline__ float4 h4f(uint2 p) {
    float2 lo = __half22float2(*reinterpret_cast<const __half2*>(&p.x));
    float2 hi = __half22float2(*reinterpret_cast<const __half2*>(&p.y));
    return make_float4(lo.x, lo.y, hi.x, hi.y);
}
__device__ __forceinline__ uint2 f4h(float4 a) {
    __half2 lo = __floats2half2_rn(a.x, a.y);
    __half2 hi = __floats2half2_rn(a.z, a.w);
    uint2 p;
    p.x = *reinterpret_cast<unsigned int*>(&lo);
    p.y = *reinterpret_cast<unsigned int*>(&hi);
    return p;
}
__device__ __forceinline__ void fma4(float4& acc, float v, float4 a) {
    acc.x = fmaf(v, a.x, acc.x);
    acc.y = fmaf(v, a.y, acc.y);
    acc.z = fmaf(v, a.z, acc.z);
    acc.w = fmaf(v, a.w, acc.w);
}

// ---------------- CSR build ----------------
// hist (six graphs) + t3 gemm1
__global__ void k_hist_all(const int* __restrict__ r11, const int* __restrict__ r22,
                           const int* __restrict__ r33, const int* __restrict__ r01,
                           const int* __restrict__ r02, const int* __restrict__ r03,
                           const float* __restrict__ f3, const float* __restrict__ W3,
                           const float* __restrict__ b3) {
    int b = blockIdx.x, t = threadIdx.x;
    if (b >= H03) {
        int r0 = (b - H03) * 4;
#pragma unroll
        for (int i = t; i < 4 * DIM; i += 256) {
            int r = r0 + (i >> 7), c = i & 127;
            float a = b3[c];
#pragma unroll 4
            for (int k = 0; k < D_POS_IN; k++)
                a = fmaf(f3[r * D_POS_IN + k], W3[k * DIM + c], a);
            g_t3a[r * DIM + c] = a;
        }
        return;
    }
    const int* rows; int E, off, b0;
    if (b < H11)      { rows = r11; E = E11; off = CU11; b0 = 0; }
    else if (b < H22) { rows = r22; E = E22; off = CU22; b0 = H11; }
    else if (b < H33) { rows = r33; E = E33; off = CU33; b0 = H22; }
    else if (b < H01) { rows = r01; E = E01; off = CU01; b0 = H33; }
    else if (b < H02) { rows = r02; E = E02; off = CU02; b0 = H01; }
    else              { rows = r03; E = E03; off = CU03; b0 = H02; }
    int e0 = (b - b0) * 1024 + t;
#pragma unroll
    for (int j = 0; j < 4; j++) {
        int e = e0 + j * 256;
        if (e < E) atomicAdd(&g_cu[off + rows[e]], 1);
    }
}

// scan (6 blocks, 1024 thr) + f1/f2 fp16 conversion (256-thr-equivalent indexing at 1024 thr)
__global__ void k_scan_all(const float* __restrict__ f1, const float* __restrict__ f2) {
    int b = blockIdx.x, tid = threadIdx.x;
    if (b >= 6) {
        if (b < SC_F1 + 625) {
            // f1 -> fp16: 640000 uint2 over 625 blocks x 1024 threads
            int idx = (b - SC_F1) * 1024 + tid;
            g_f1h[idx] = f4h(((const float4*)f1)[idx]);
        } else {
            int idx = (b - SC_F1 - 625) * 1024 + tid;
            if (idx < N_ENT * 32) g_f2h[idx] = f4h(((const float4*)f2)[idx]);
        }
        return;
    }
    __shared__ int wsum[32];
    const int ns[6]  = {N_WORD, N_ENT, N_POS, N_DOC, N_DOC, N_DOC};
    const int cuo[6] = {CU11, CU22, CU33, CU01, CU02, CU03};
    const int rpo[6] = {RP11, RP22, RP33, RP01, RP02, RP03};
    int n = ns[b];
    int* cnt = g_cu + cuo[b];
    int* rp  = g_rp + rpo[b];
    int chunk = (n + 1023) >> 10;
    int base = tid * chunk;
    int end = base + chunk; if (end > n) end = n;
    int s = 0;
    for (int i = base; i < end && i >= base; i++) s += cnt[i];
    int lane = tid & 31, w = tid >> 5;
    int v = s;
#pragma unroll
    for (int o = 1; o < 32; o <<= 1) { int u = __shfl_up_sync(~0u, v, o); if (lane >= o) v += u; }
    if (lane == 31) wsum[w] = v;
    __syncthreads();
    if (w == 0) {
        int x = wsum[lane];
#pragma unroll
        for (int o = 1; o < 32; o <<= 1) { int u = __shfl_up_sync(~0u, x, o); if (lane >= o) x += u; }
        wsum[lane] = x;
    }
    __syncthreads();
    int excl = v - s + (w > 0 ? wsum[w - 1] : 0);
    int run = excl;
    for (int i = base; i < end && i >= base; i++) {
        int c = cnt[i];
        cnt[i] = run;
        rp[i] = run;
        run += c;
    }
    if (end == n || base >= n) rp[n] = run;
}

__device__ __forceinline__ void scatter_range(const int* __restrict__ rows, const int* __restrict__ cols,
                                              const float* __restrict__ vals, int E, int cuoff, int eoff,
                                              int rel_b, int t) {
    int e0 = rel_b * 1024 + t;
#pragma unroll
    for (int j = 0; j < 4; j++) {
        int e = e0 + j * 256;
        if (e < E) {
            int slot = atomicAdd(&g_cu[cuoff + rows[e]], 1);
            g_ecv[eoff + slot] = make_int2(cols[e], __float_as_int(vals[e]));
        }
    }
}

__global__ void k_scatter_all(const int* __restrict__ r11, const int* __restrict__ c11, const float* __restrict__ v11,
                              const int* __restrict__ r22, const int* __restrict__ c22, const float* __restrict__ v22,
                              const int* __restrict__ r33, const int* __restrict__ c33, const float* __restrict__ v33,
                              const int* __restrict__ r01, const int* __restrict__ c01, const float* __restrict__ v01,
                              const int* __restrict__ r02, const int* __restrict__ c02, const float* __restrict__ v02,
                              const int* __restrict__ r03, const int* __restrict__ c03, const float* __restrict__ v03) {
    int b = blockIdx.x, t = threadIdx.x;
    if (b < H11)      scatter_range(r11, c11, v11, E11, CU11, EO11, b, t);
    else if (b < H22) scatter_range(r22, c22, v22, E22, CU22, EO22, b - H11, t);
    else if (b < H33) scatter_range(r33, c33, v33, E33, CU33, EO33, b - H22, t);
    else if (b < H01) scatter_range(r01, c01, v01, E01, CU01, EO01, b - H33, t);
    else if (b < H02) scatter_range(r02, c02, v02, E02, CU02, EO02, b - H01, t);
    else              scatter_range(r03, c03, v03, E03, CU03, EO03, b - H02, t);
}

// ---------------- spMM cores: warp per row, lane holds 4 cols, x4 unroll ----------------
__device__ __forceinline__ float4 spmm_row_f4(const int* __restrict__ rp, const int2* __restrict__ ecv,
                                              const float4* __restrict__ x4, int row, int lane) {
    int s = rp[row], e = rp[row + 1];
    float4 acc = make_float4(0.f, 0.f, 0.f, 0.f);
    int i = s;
    for (; i + 3 < e; i += 4) {
        int2 e0 = ecv[i], e1 = ecv[i + 1], e2 = ecv[i + 2], e3 = ecv[i + 3];
        float4 a = x4[(size_t)e0.x * 32 + lane];
        float4 b = x4[(size_t)e1.x * 32 + lane];
        float4 c = x4[(size_t)e2.x * 32 + lane];
        float4 d = x4[(size_t)e3.x * 32 + lane];
        fma4(acc, __int_as_float(e0.y), a);
        fma4(acc, __int_as_float(e1.y), b);
        fma4(acc, __int_as_float(e2.y), c);
        fma4(acc, __int_as_float(e3.y), d);
    }
    for (; i < e; i++) {
        int2 e0 = ecv[i];
        fma4(acc, __int_as_float(e0.y), x4[(size_t)e0.x * 32 + lane]);
    }
    return acc;
}

__device__ __forceinline__ float4 spmm_row_h4(const int* __restrict__ rp, const int2* __restrict__ ecv,
                                              const uint2* __restrict__ xh, int row, int lane) {
    int s = rp[row], e = rp[row + 1];
    float4 acc = make_float4(0.f, 0.f, 0.f, 0.f);
    int i = s;
    for (; i + 3 < e; i += 4) {
        int2 e0 = ecv[i], e1 = ecv[i + 1], e2 = ecv[i + 2], e3 = ecv[i + 3];
        uint2 pa = xh[(size_t)e0.x * 32 + lane];
        uint2 pb = xh[(size_t)e1.x * 32 + lane];
        uint2 pc = xh[(size_t)e2.x * 32 + lane];
        uint2 pd = xh[(size_t)e3.x * 32 + lane];
        fma4(acc, __int_as_float(e0.y), h4f(pa));
        fma4(acc, __int_as_float(e1.y), h4f(pb));
        fma4(acc, __int_as_float(e2.y), h4f(pc));
        fma4(acc, __int_as_float(e3.y), h4f(pd));
    }
    for (; i < e; i++) {
        int2 e0 = ecv[i];
        fma4(acc, __int_as_float(e0.y), h4f(xh[(size_t)e0.x * 32 + lane]));
    }
    return acc;
}

__device__ __forceinline__ void store_relu_f4(float4 acc, float* __restrict__ y, int row, int lane) {
    ((float4*)y)[(size_t)row * 32 + lane] =
        make_float4(fmaxf(acc.x, 0.f), fmaxf(acc.y, 0.f), fmaxf(acc.z, 0.f), fmaxf(acc.w, 0.f));
}

__device__ __forceinline__ void store_relu_h4(float4 a, uint2* __restrict__ y, int row, int lane) {
    y[(size_t)row * 32 + lane] =
        f4h(make_float4(fmaxf(a.x, 0.f), fmaxf(a.y, 0.f), fmaxf(a.z, 0.f), fmaxf(a.w, 0.f)));
}

__device__ __forceinline__ void store_norm_f4(float4 acc, float* __restrict__ y, int row, int lane) {
    float sq = acc.x * acc.x + acc.y * acc.y + acc.z * acc.z + acc.w * acc.w;
#pragma unroll
    for (int o = 16; o > 0; o >>= 1) sq += __shfl_xor_sync(~0u, sq, o);
    float s = 1.f / (sqrtf(sq) + 1e-9f);
    ((float4*)y)[(size_t)row * 32 + lane] = make_float4(acc.x * s, acc.y * s, acc.z * s, acc.w * s);
}

// ---------------- Stage A: spmm1(t1) + spmm1(t2) from fp16 inputs + t3 spmm1 ----------------
__global__ void __launch_bounds__(256, 8) k_stageA() {
    int b = blockIdx.x, t = threadIdx.x, lane = t & 31, w = t >> 5;
    if (b < 2500) {
        int row = b * 8 + w;
        float4 acc = spmm_row_h4(g_rp + RP11, g_ecv + EO11, g_f1h, row, lane);
        store_relu_f4(acc, g_h1a, row, lane);
    } else if (b < 3750) {
        int row = (b - 2500) * 8 + w;
        float4 acc = spmm_row_h4(g_rp + RP22, g_ecv + EO22, g_f2h, row, lane);
        store_relu_f4(acc, g_h2a, row, lane);
    } else {
        int row = (b - 3750) * 8 + w;
        if (row < N_POS) {
            float4 acc = spmm_row_f4(g_rp + RP33, g_ecv + EO33, (const float4*)g_t3a, row, lane);
            store_relu_f4(acc, g_t3b, row, lane);
        }
    }
}

// ---------------- FFMA2 GEMM, 64-row tiles: y = x @ W + b (fp32 or fp16 output) ----------------
template <bool HALF_OUT>
__device__ __forceinline__ void gemm64_f2(const float* __restrict__ x, const float* __restrict__ W,
                                          const float* __restrict__ bias, float* __restrict__ y,
                                          uint2* __restrict__ yh, int nrows, int r0, float* xs) {
    int t = threadIdx.x;
    const float4* x4 = (const float4*)x;
    float4* xs4 = (float4*)xs;
    for (int i = t; i < 64 * 32; i += 256) {
        int gr = r0 + (i >> 5);
        xs4[i] = (gr < nrows) ? x4[(size_t)gr * 32 + (i & 31)] : make_float4(0.f, 0.f, 0.f, 0.f);
    }
    __syncthreads();
    int cg = t & 31;
    int rg = t >> 5;
    const float4* Wc = (const float4*)W;
    float4 b4 = ((const float4*)bias)[cg];
    ull acc[8][2];
#pragma unroll
    for (int r = 0; r < 8; r++) { acc[r][0] = pack2(b4.x, b4.y); acc[r][1] = pack2(b4.z, b4.w); }
    const float4* xr = xs4 + rg * 8 * 32;
    for (int k4 = 0; k4 < 32; k4++) {
        float4 xv[8];
#pragma unroll
        for (int r = 0; r < 8; r++) xv[r] = xr[r * 32 + k4];
#pragma unroll
        for (int kk = 0; kk < 4; kk++) {
            float4 wv = Wc[(k4 * 4 + kk) * 32 + cg];
            ull wp0 = pack2(wv.x, wv.y);
            ull wp1 = pack2(wv.z, wv.w);
#pragma unroll
            for (int r = 0; r < 8; r++) {
                float xsv = (kk == 0) ? xv[r].x : (kk == 1) ? xv[r].y : (kk == 2) ? xv[r].z : xv[r].w;
                ull xp = pack2(xsv, xsv);
                acc[r][0] = fma2(xp, wp0, acc[r][0]);
                acc[r][1] = fma2(xp, wp1, acc[r][1]);
            }
        }
    }
#pragma unroll
    for (int r = 0; r < 8; r++) {
        int gr = r0 + rg * 8 + r;
        if (gr < nrows) {
            float2 lo = unpack2(acc[r][0]);
            float2 hi = unpack2(acc[r][1]);
            if (HALF_OUT) {
                yh[(size_t)gr * 32 + cg] = f4h(make_float4(lo.x, lo.y, hi.x, hi.y));
            } else {
                ((float4*)y)[(size_t)gr * 32 + cg] = make_float4(lo.x, lo.y, hi.x, hi.y);
            }
        }
    }
}

// ---------------- Stage B: gemms (FMA-bound) + warp-per-row wemb doc-aggregation ----------------
__global__ void k_stageB(const float* __restrict__ wemb,
                         const float* __restrict__ W1_2, const float* __restrict__ b1_2,
                         const float* __restrict__ W2_2, const float* __restrict__ b2_2,
                         const float* __restrict__ W3_2, const float* __restrict__ b3_2) {
    __shared__ float xs[64 * 128];
    int b = blockIdx.x, t = threadIdx.x;
    if (b < BG1)      { gemm64_f2<true>(g_h1a, W1_2, b1_2, nullptr, g_t1h, N_WORD, b * 64, xs); return; }
    else if (b < BG2) { gemm64_f2<true>(g_h2a, W2_2, b2_2, nullptr, g_t2h, N_ENT, (b - BG1) * 64, xs); return; }
    else if (b < BG3) { gemm64_f2<false>(g_t3b, W3_2, b3_2, g_t3a, nullptr, N_POS, 0, xs); return; }
    int lane = t & 31, w = t >> 5;
    int row = (b - B_AGG0) * 8 + w;
    if (row < N_DOC) {
        int s = g_rp[RP02 + row], e = g_rp[RP02 + row + 1];
        float acc[10];
#pragma unroll
        for (int j = 0; j < 10; j++) acc[j] = 0.f;
        for (int i = s; i < e; i++) {
            int2 ed = g_ecv[EO02 + i];
            float v = __int_as_float(ed.y);
            const float* wrow = wemb + (size_t)ed.x * D_WEMB;
#pragma unroll
            for (int j = 0; j < 10; j++) {
                int c = lane + j * 32;
                if (c < D_WEMB) acc[j] = fmaf(v, wrow[c], acc[j]);
            }
        }
        float* orow = g_w2agg + (size_t)row * D_WEMB;
#pragma unroll
        for (int j = 0; j < 10; j++) {
            int c = lane + j * 32;
            if (c < D_WEMB) orow[c] = acc[j];
        }
    }
}

// ---------------- Stage C: spmm2 from fp16 t1/t2, outputs fp16 ----------------
__global__ void __launch_bounds__(256, 8) k_stageC() {
    int b = blockIdx.x, t = threadIdx.x, lane = t & 31, w = t >> 5;
    if (b < 2500) {
        int row = b * 8 + w;
        float4 acc = spmm_row_h4(g_rp + RP11, g_ecv + EO11, g_t1h, row, lane);
        store_relu_h4(acc, g_h1h, row, lane);
    } else if (b < 3750) {
        int row = (b - 2500) * 8 + w;
        float4 acc = spmm_row_h4(g_rp + RP22, g_ecv + EO22, g_t2h, row, lane);
        store_relu_h4(acc, g_h2h, row, lane);
    } else {
        int row = (b - 3750) * 8 + w;
        if (row < N_POS) {
            float4 acc = spmm_row_f4(g_rp + RP33, g_ecv + EO33, (const float4*)g_t3a, row, lane);
            store_relu_h4(acc, g_h3h, row, lane);
        }
    }
}

// ---------------- Stage D (448 thr, 14 warps): warp-per-row out1/out2/out3 (fp16 gathers) ----------------
__global__ void k_stageD(float* __restrict__ out) {
    int b = blockIdx.x, t = threadIdx.x, lane = t & 31, w = t >> 5;
    if (b < D_OUT1) {
        int row = b * 14 + w;
        if (row < N_DOC) {
            float4 acc = spmm_row_h4(g_rp + RP01, g_ecv + EO01, g_h1h, row, lane);
            store_norm_f4(acc, out, row, lane);
        }
    } else if (b < D_OUT2) {
        int row = (b - D_OUT1) * 14 + w;
        if (row < N_DOC) {
            float4 acc = spmm_row_h4(g_rp + RP02, g_ecv + EO02, g_h2h, row, lane);
            float sq = acc.x * acc.x + acc.y * acc.y + acc.z * acc.z + acc.w * acc.w;
            float wv[10];
            const float* wrow = g_w2agg + (size_t)row * D_WEMB;
#pragma unroll
            for (int j = 0; j < 10; j++) {
                int c = lane + j * 32;
                wv[j] = (c < D_WEMB) ? wrow[c] : 0.f;
                sq = fmaf(wv[j], wv[j], sq);
            }
#pragma unroll
            for (int o = 16; o > 0; o >>= 1) sq += __shfl_xor_sync(~0u, sq, o);
            float sc = 1.f / (sqrtf(sq) + 1e-9f);
            float* orow = out + (size_t)N_DOC * DIM + (size_t)row * (DIM + D_WEMB);
            ((float4*)orow)[lane] = make_float4(acc.x * sc, acc.y * sc, acc.z * sc, acc.w * sc);
#pragma unroll
            for (int j = 0; j < 10; j++) {
                int c = lane + j * 32;
                if (c < D_WEMB) orow[DIM + c] = wv[j] * sc;
            }
        }
    } else if (b < D_OUT3) {
        int row = (b - D_OUT2) * 14 + w;
        if (row < N_DOC) {
            float4 acc = spmm_row_h4(g_rp + RP03, g_ecv + EO03, g_h3h, row, lane);
            float* out3 = out + (size_t)N_DOC * (DIM + DIM + D_WEMB);
            store_norm_f4(acc, out3, row, lane);
        }
    } else {
        int base = (b - D_OUT3) * 1024;
#pragma unroll
        for (int i = t; i < 1024; i += 448) {
            int idx = base + i;
            if (idx < CU_TOT) g_cu[idx] = 0;
        }
    }
}

// ---------------- host ----------------
extern "C" void kernel_launch(void* const* d_in, const int* in_sizes, int n_in,
                              void* d_out, int out_size) {
    const float* f1 = (const float*)d_in[0];
    const float* f2 = (const float*)d_in[1];
    const float* f3 = (const float*)d_in[2];
    const float* wemb = (const float*)d_in[3];
    const int* a11_r = (const int*)d_in[4];  const int* a11_c = (const int*)d_in[5];  const float* a11_v = (const float*)d_in[6];
    const int* a22_r = (const int*)d_in[7];  const int* a22_c = (const int*)d_in[8];  const float* a22_v = (const float*)d_in[9];
    const int* a33_r = (const int*)d_in[10]; const int* a33_c = (const int*)d_in[11]; const float* a33_v = (const float*)d_in[12];
    const int* a01_r = (const int*)d_in[13]; const int* a01_c = (const int*)d_in[14]; const float* a01_v = (const float*)d_in[15];
    const int* a02_r = (const int*)d_in[16]; const int* a02_c = (const int*)d_in[17]; const float* a02_v = (const float*)d_in[18];
    const int* a03_r = (const int*)d_in[19]; const int* a03_c = (const int*)d_in[20]; const float* a03_v = (const float*)d_in[21];
    const float* W3 = (const float*)d_in[22];   const float* b3 = (const float*)d_in[23];
    const float* W1_2 = (const float*)d_in[24]; const float* b1_2 = (const float*)d_in[25];
    const float* W2_2 = (const float*)d_in[26]; const float* b2_2 = (const float*)d_in[27];
    const float* W3_2 = (const float*)d_in[28]; const float* b3_2 = (const float*)d_in[29];

    float* out = (float*)d_out;

    // CSR build (g_cu zeroed by BSS init on first run, by stageD on every replay)
    k_hist_all<<<HT3, 256>>>(a11_r, a22_r, a33_r, a01_r, a02_r, a03_r, f3, W3, b3);
    k_scan_all<<<SC_TOT, 1024>>>(f1, f2);
    k_scatter_all<<<H03, 256>>>(a11_r, a11_c, a11_v, a22_r, a22_c, a22_v,
                                a33_r, a33_c, a33_v, a01_r, a01_c, a01_v,
                                a02_r, a02_c, a02_v, a03_r, a03_c, a03_v);

    // compute
    k_stageA<<<3758, 256>>>();
    k_stageB<<<B_TOT, 256>>>(wemb, W1_2, b1_2, W2_2, b2_2, W3_2, b3_2);
    k_stageC<<<3758, 256>>>();
    k_stageD<<<D_ZERO, 448>>>(out);
}